// round 1
// baseline (speedup 1.0000x reference)
#include <cuda_runtime.h>
#include <cstdint>

// Problem constants (shapes are fixed by the dataset)
#define B_SZ    64
#define D_SZ    920        // 23*40 flattened attention
#define K_SEL   32
#define N_SAMP  920        // num_samples == d
#define NROWS   (B_SZ * D_SZ)   // 58880 sample-rows (b, n)
#define THREADS 256
#define CAND_MAX 512

// 1 = modern JAX (jax_threefry_partitionable=True): bits[g] = o0^o1 of tf((0,1),(0,g))
// 0 = legacy: split-iota halves (not compiled in; toggle if rel_err says so)
#define NOISE_PARTITIONABLE 1

// Per-row selected wa values: scratch[row*32 + k] ; 58880*32 floats = 7.5MB
__device__ float g_scratch[NROWS * K_SEL];

// ---------------- threefry2x32, key = (0, 1)  (jax.random.key(1)) -------------
__device__ __forceinline__ unsigned tf_bits_partitionable(unsigned ctr) {
    // x = (0, ctr). ks = [0, 1, 0^1^0x1BD11BDA = 0x1BD11BDB]
    unsigned x0 = 0u, x1 = ctr;
    const unsigned k0 = 0u, k1 = 1u, kx = 0x1BD11BDBu;
    x0 += k0; x1 += k1;
#define TFR(r) { x0 += x1; x1 = __funnelshift_l(x1, x1, (r)); x1 ^= x0; }
    TFR(13) TFR(15) TFR(26) TFR(6)
    x0 += k1; x1 += kx + 1u;
    TFR(17) TFR(29) TFR(16) TFR(24)
    x0 += kx; x1 += k0 + 2u;
    TFR(13) TFR(15) TFR(26) TFR(6)
    x0 += k0; x1 += k1 + 3u;
    TFR(17) TFR(29) TFR(16) TFR(24)
    x0 += k1; x1 += kx + 4u;
#undef TFR
#if NOISE_PARTITIONABLE
    return x0 ^ x1;     // 32-bit fold of the 64-bit block (partitionable path)
#else
    return x0;
#endif
}

// ---------------- XLA ErfInv32 (Giles), exact coefficients --------------------
__device__ __forceinline__ float erfinv_xla(float x) {
    float w = -log1pf(-__fmul_rn(x, x));
    float p;
    if (w < 5.0f) {
        w = w - 2.5f;
        p = 2.81022636e-08f;
        p = fmaf(p, w, 3.43273939e-07f);
        p = fmaf(p, w, -3.5233877e-06f);
        p = fmaf(p, w, -4.39150654e-06f);
        p = fmaf(p, w, 0.00021858087f);
        p = fmaf(p, w, -0.00125372503f);
        p = fmaf(p, w, -0.00417768164f);
        p = fmaf(p, w, 0.246640727f);
        p = fmaf(p, w, 1.50140941f);
    } else {
        w = sqrtf(w) - 3.0f;
        p = -0.000200214257f;
        p = fmaf(p, w, 0.000100950558f);
        p = fmaf(p, w, 0.00134934322f);
        p = fmaf(p, w, -0.00367342844f);
        p = fmaf(p, w, 0.00573950773f);
        p = fmaf(p, w, -0.0076224613f);
        p = fmaf(p, w, 0.00943887047f);
        p = fmaf(p, w, 1.00167406f);
        p = fmaf(p, w, 2.83297682f);
    }
    return __fmul_rn(p, x);
}

// noise = sqrt(2) * erfinv( u01*2 - 0.99999994 ),  u01 = [0,1) from top-23 bits
__device__ __forceinline__ float normal_from_bits(unsigned bits) {
    float f = __uint_as_float((bits >> 9) | 0x3F800000u) - 1.0f;   // [0,1)
    // (maxval-minval) rounds to exactly 2.0f in fp32; *2 is exact, so fma-safe,
    // but keep explicit rn ops to mirror XLA's mul-then-add.
    float u = __fadd_rn(__fmul_rn(f, 2.0f), -0.99999994f);
    return __fmul_rn(1.41421356f, erfinv_xla(u));
}

__device__ __forceinline__ unsigned orderable(float v) {
    unsigned u = __float_as_uint(v);
    return (u & 0x80000000u) ? ~u : (u | 0x80000000u);
}

// =============================================================================
// Kernel 1: one CTA per sample-row (b, n).
//   gen 920 noise vals -> perturbed keys -> 2-level radix top-32 (set, with
//   lax.top_k tie-break) -> ranks by ascending index -> scratch[row*32+k]=wa[d_k]
// =============================================================================
__global__ void __launch_bounds__(THREADS)
row_topk_kernel(const float* __restrict__ wa /* (64, 920) */) {
    const int rp  = blockIdx.x;          // b*920 + n
    const int b   = rp / D_SZ;
    const int tid = threadIdx.x;

    __shared__ float     s_wa[D_SZ];
    __shared__ unsigned  s_key[D_SZ];
    __shared__ unsigned  s_hist[256];
    __shared__ unsigned  s_wtot[8];
    __shared__ unsigned  s_mask[29];
    __shared__ unsigned  s_psum[32];
    __shared__ unsigned long long s_cand[CAND_MAX];
    __shared__ unsigned  s_scalar[8];    // 0:B1 1:above1 2:B2 3:above2 4:cnt

    const float* warow = wa + (size_t)b * D_SZ;
    for (int d = tid; d < D_SZ; d += THREADS) s_wa[d] = warow[d];
    s_hist[tid] = 0u;
    if (tid == 0) s_scalar[4] = 0u;
    __syncthreads();

    // ---- noise + keys + pass-1 histogram (top 8 bits of orderable key) ----
    const unsigned gbase = (unsigned)rp * (unsigned)D_SZ;   // flat noise index base
    for (int d = tid; d < D_SZ; d += THREADS) {
        unsigned bits = tf_bits_partitionable(gbase + (unsigned)d);
        float nrm  = normal_from_bits(bits);
        float pert = __fadd_rn(s_wa[d], __fmul_rn(nrm, 0.1f));   // x + noise*sigma
        unsigned key = orderable(pert);
        s_key[d] = key;
        atomicAdd(&s_hist[key >> 24], 1u);
    }
    __syncthreads();

    // ---- suffix-scan select helper over 256 bins (all 256 threads) ----
    auto suffix_find = [&](unsigned target, int out_base) {
        unsigned v = s_hist[tid];
        unsigned lane = tid & 31u, w = tid >> 5;
        unsigned x = v;
        #pragma unroll
        for (int off = 1; off < 32; off <<= 1) {
            unsigned y = __shfl_down_sync(0xFFFFFFFFu, x, off);
            if (lane + off < 32) x += y;
        }
        if (lane == 0) s_wtot[w] = x;
        __syncthreads();
        unsigned hi = 0;
        for (unsigned ww = w + 1; ww < 8; ww++) hi += s_wtot[ww];
        unsigned incl  = x + hi;        // count of bins >= tid
        unsigned above = incl - v;      // count of bins  > tid
        if (above < target && incl >= target) {
            s_scalar[out_base]     = (unsigned)tid;
            s_scalar[out_base + 1] = above;
        }
        __syncthreads();
    };

    suffix_find(K_SEL, 0);
    const unsigned B1 = s_scalar[0], above1 = s_scalar[1];

    // ---- pass-2 histogram (bits [16,24)) among keys in bin B1 ----
    s_hist[tid] = 0u;
    __syncthreads();
    for (int d = tid; d < D_SZ; d += THREADS) {
        unsigned key = s_key[d];
        if ((key >> 24) == B1) atomicAdd(&s_hist[(key >> 16) & 0xFFu], 1u);
    }
    __syncthreads();
    suffix_find(K_SEL - above1, 2);
    const unsigned B2 = s_scalar[2];
    const unsigned need = K_SEL - above1 - s_scalar[3];   // from the boundary bin
    const unsigned P16 = (B1 << 8) | B2;

    if (tid < 29) s_mask[tid] = 0u;
    __syncthreads();

    // ---- definite winners -> mask; boundary-bin keys -> candidate list ----
    for (int d = tid; d < D_SZ; d += THREADS) {
        unsigned hk = s_key[d] >> 16;
        if (hk > P16) {
            atomicOr(&s_mask[d >> 5], 1u << (d & 31));
        } else if (hk == P16) {
            unsigned pos = atomicAdd(&s_scalar[4], 1u);
            if (pos < CAND_MAX)   // larger = better: (key desc, index asc)
                s_cand[pos] = ((unsigned long long)s_key[d] << 32) | (unsigned)(~d);
        }
    }
    __syncthreads();

    const unsigned m = min(s_scalar[4], (unsigned)CAND_MAX);
    if (m <= need) {
        // whole boundary bin is selected
        if (tid < m) {
            unsigned d = ~(unsigned)(s_cand[tid] & 0xFFFFFFFFull);
            atomicOr(&s_mask[d >> 5], 1u << (d & 31));
        }
    } else if (tid < 32) {
        // warp 0: pick top `need` by (full key desc, index asc) — matches lax.top_k ties
        for (unsigned it = 0; it < need; it++) {
            unsigned long long best = 0ull; int bpos = -1;
            for (unsigned j = tid; j < m; j += 32)
                if (s_cand[j] > best) { best = s_cand[j]; bpos = (int)j; }
            #pragma unroll
            for (int off = 16; off; off >>= 1) {
                unsigned long long ob = __shfl_down_sync(0xFFFFFFFFu, best, off);
                int op = __shfl_down_sync(0xFFFFFFFFu, bpos, off);
                if (ob > best) { best = ob; bpos = op; }
            }
            if (tid == 0) {
                unsigned d = ~(unsigned)(best & 0xFFFFFFFFull);
                s_cand[bpos] = 0ull;
                atomicOr(&s_mask[d >> 5], 1u << (d & 31));
            }
            __syncwarp();
        }
    }
    __syncthreads();

    // ---- exclusive prefix of popcounts -> ascending-index ranks ----
    if (tid < 32) {
        unsigned v = (tid < 29) ? __popc(s_mask[tid]) : 0u;
        unsigned acc = v;
        #pragma unroll
        for (int off = 1; off < 32; off <<= 1) {
            unsigned y = __shfl_up_sync(0xFFFFFFFFu, acc, off);
            if (tid >= off) acc += y;
        }
        s_psum[tid] = acc - v;
    }
    __syncthreads();

    for (int d = tid; d < D_SZ; d += THREADS) {
        unsigned wd = d >> 5, bit = d & 31;
        unsigned mw = s_mask[wd];
        if (mw & (1u << bit)) {
            unsigned rank = s_psum[wd] + __popc(mw & ((1u << bit) - 1u));
            g_scratch[(size_t)rp * K_SEL + rank] = s_wa[d];
        }
    }
}

// =============================================================================
// Kernel 2: per-b reduce over 920 samples, then bbox. Deterministic sums.
// out[b][k] = [x0, y0, x1, y1]
// =============================================================================
__global__ void __launch_bounds__(256)
finalize_kernel(float* __restrict__ out) {
    const int b = blockIdx.x;
    const int tid = threadIdx.x;
    const int lane = tid & 31;   // k
    const int w = tid >> 5;      // 8 sample groups
    __shared__ float red[8][32];

    const float* base = g_scratch + (size_t)b * N_SAMP * K_SEL;
    float acc = 0.0f;
    for (int n = w; n < N_SAMP; n += 8)
        acc += base[n * K_SEL + lane];      // coalesced 128B per warp
    red[w][lane] = acc;
    __syncthreads();

    if (w == 0) {
        float s = 0.0f;
        #pragma unroll
        for (int i = 0; i < 8; i++) s += red[i][lane];
        s = s / (float)N_SAMP;

        float r = floorf(__fdiv_rn(s, 40.0f));
        float c = __fadd_rn(s, -__fmul_rn(r, 40.0f));   // jnp.mod(s, 40)
        float x0 = __fmul_rn((c < 1.0f) ? c : (c - 1.0f), 32.0f);
        float y0 = __fmul_rn((r < 1.0f) ? r : (r - 1.0f), 32.0f);
        float x1 = __fmul_rn((c < 1.0f) ? (c + 2.0f) : (c + 1.0f), 32.0f);
        float y1 = __fmul_rn(r + 2.0f, 32.0f);
        float4 v = make_float4(x0, y0, x1, y1);
        reinterpret_cast<float4*>(out)[b * K_SEL + lane] = v;
    }
}

extern "C" void kernel_launch(void* const* d_in, const int* in_sizes, int n_in,
                              void* d_out, int out_size) {
    (void)in_sizes; (void)n_in; (void)out_size;
    const float* weight_attn = (const float*)d_in[2];   // (64, 23, 40) -> (64, 920)
    float* out = (float*)d_out;                          // (64, 32, 4)

    row_topk_kernel<<<NROWS, THREADS>>>(weight_attn);
    finalize_kernel<<<B_SZ, 256>>>(out);
}

// round 2
// speedup vs baseline: 1.5967x; 1.5967x over previous
#include <cuda_runtime.h>
#include <cstdint>

// ---------------- problem constants ----------------
#define B_SZ    64
#define D_SZ    920          // 23*40
#define K_SEL   32
#define NROWS   (B_SZ * D_SZ)      // 58880 sample-rows (b, n)
#define WARPS_PER_CTA 8
#define THREADS (WARPS_PER_CTA * 32)
#define CAP     256          // candidate capacity per warp
#define T0_INIT 0.90f        // prefilter threshold (runtime-validated, exact fallback)

// selected indices: g_sel[row*32 + k] = d ; 58880*32 u16 = 3.68MB
__device__ unsigned short g_sel[NROWS * K_SEL];

// ---------------- threefry2x32, key = (0,1), partitionable fold --------------
__device__ __forceinline__ unsigned tf_bits(unsigned ctr) {
    unsigned x0 = 0u, x1 = ctr;
    const unsigned k0 = 0u, k1 = 1u, kx = 0x1BD11BDBu;
    x0 += k0; x1 += k1;
#define TFR(r) { x0 += x1; x1 = __funnelshift_l(x1, x1, (r)); x1 ^= x0; }
    TFR(13) TFR(15) TFR(26) TFR(6)
    x0 += k1; x1 += kx + 1u;
    TFR(17) TFR(29) TFR(16) TFR(24)
    x0 += kx; x1 += k0 + 2u;
    TFR(13) TFR(15) TFR(26) TFR(6)
    x0 += k0; x1 += k1 + 3u;
    TFR(17) TFR(29) TFR(16) TFR(24)
    x0 += k1; x1 += kx + 4u;
#undef TFR
    return x0 ^ x1;
}

// ---------------- XLA ErfInv32 (identical numerics to passing round) ---------
__device__ __forceinline__ float erfinv_xla(float x) {
    float w = -log1pf(-__fmul_rn(x, x));
    float p;
    if (w < 5.0f) {
        w = w - 2.5f;
        p = 2.81022636e-08f;
        p = fmaf(p, w, 3.43273939e-07f);
        p = fmaf(p, w, -3.5233877e-06f);
        p = fmaf(p, w, -4.39150654e-06f);
        p = fmaf(p, w, 0.00021858087f);
        p = fmaf(p, w, -0.00125372503f);
        p = fmaf(p, w, -0.00417768164f);
        p = fmaf(p, w, 0.246640727f);
        p = fmaf(p, w, 1.50140941f);
    } else {
        w = sqrtf(w) - 3.0f;
        p = -0.000200214257f;
        p = fmaf(p, w, 0.000100950558f);
        p = fmaf(p, w, 0.00134934322f);
        p = fmaf(p, w, -0.00367342844f);
        p = fmaf(p, w, 0.00573950773f);
        p = fmaf(p, w, -0.0076224613f);
        p = fmaf(p, w, 0.00943887047f);
        p = fmaf(p, w, 1.00167406f);
        p = fmaf(p, w, 2.83297682f);
    }
    return __fmul_rn(p, x);
}

__device__ __forceinline__ float normal_from_bits(unsigned bits) {
    float f = __uint_as_float((bits >> 9) | 0x3F800000u) - 1.0f;   // [0,1)
    float u = __fadd_rn(__fmul_rn(f, 2.0f), -0.99999994f);
    return __fmul_rn(1.41421356f, erfinv_xla(u));
}

__device__ __forceinline__ unsigned orderable(float v) {
    unsigned u = __float_as_uint(v);
    return (u & 0x80000000u) ? ~u : (u | 0x80000000u);
}
__device__ __forceinline__ float inv_orderable(unsigned k) {
    unsigned u = (k & 0x80000000u) ? (k & 0x7FFFFFFFu) : ~k;
    return __uint_as_float(u);
}
// monotone quantizer (fine bins over the competitive range ~[0.87, 1.29])
__device__ __forceinline__ int qbin_of(float pert) {
    int q = (int)fmaf(pert, 600.0f, -520.0f);
    return min(255, max(0, q));
}

__device__ __forceinline__ float make_pert(const float* s_wa, unsigned gbase, int d) {
    unsigned bits = tf_bits(gbase + (unsigned)d);
    float nrm = normal_from_bits(bits);
    return __fadd_rn(s_wa[d], __fmul_rn(nrm, 0.1f));
}

// gen pass: count (and optionally collect) elements with pert > T0
template<bool STORE>
__device__ __forceinline__ int gen_pass(const float* s_wa, unsigned gbase, float T0,
                                        unsigned long long* cand, int lane) {
    const unsigned ltmask = (1u << lane) - 1u;
    int base = 0;
    for (int i = 0; i < 28; ++i) {                 // 28 full iterations
        int d = (i << 5) + lane;
        float pert = make_pert(s_wa, gbase, d);
        bool pred = (pert > T0);
        unsigned bal = __ballot_sync(0xFFFFFFFFu, pred);
        if (STORE && pred) {
            int slot = base + __popc(bal & ltmask);
            if (slot < CAP)
                cand[slot] = ((unsigned long long)orderable(pert) << 32) | (unsigned)(~d);
        }
        base += __popc(bal);
    }
    {   // tail: d = 896 + lane, valid for lane < 24
        int d = 896 + lane;
        bool valid = (d < D_SZ);
        float pert = valid ? make_pert(s_wa, gbase, d) : -1e30f;
        bool pred = valid && (pert > T0);
        unsigned bal = __ballot_sync(0xFFFFFFFFu, pred);
        if (STORE && pred) {
            int slot = base + __popc(bal & ltmask);
            if (slot < CAP)
                cand[slot] = ((unsigned long long)orderable(pert) << 32) | (unsigned)(~d);
        }
        base += __popc(bal);
    }
    return base;
}

// =============================================================================
// Kernel 1: warp-per-row. 8 rows per CTA (all same b since 920 % 8 == 0).
// =============================================================================
__global__ void __launch_bounds__(THREADS)
row_topk_kernel(const float* __restrict__ wa) {
    __shared__ float              s_wa[D_SZ];
    __shared__ unsigned long long s_cand[WARPS_PER_CTA][CAP];
    __shared__ unsigned           s_hist[WARPS_PER_CTA][256];
    __shared__ unsigned char      s_qb[WARPS_PER_CTA][CAP];
    __shared__ unsigned           s_sel[WARPS_PER_CTA][K_SEL];
    __shared__ unsigned           s_chosen[WARPS_PER_CTA][CAP / 32];

    const int tid  = threadIdx.x;
    const int w    = tid >> 5;
    const int lane = tid & 31;
    const int row  = blockIdx.x * WARPS_PER_CTA + w;
    const int b    = (blockIdx.x * WARPS_PER_CTA) / D_SZ;   // same for whole CTA

    const float* warow = wa + (size_t)b * D_SZ;
    for (int d = tid; d < D_SZ; d += THREADS) s_wa[d] = warow[d];
    __syncthreads();            // the only block barrier

    unsigned long long* cand = s_cand[w];
    const unsigned gbase = (unsigned)row * (unsigned)D_SZ;

    // ---- fused generate + prefilter ----
    float T0 = T0_INIT;
    int m = gen_pass<true>(s_wa, gbase, T0, cand, lane);

    if (m < K_SEL || m > CAP) {
        // exact fallback: bisect a threshold with K_SEL <= m <= CAP (never fires
        // for this input distribution, but guarantees correctness in general)
        float lo = -0.7f, hi = 1.6f;   // count(lo) = 920, count(hi) = 0
        for (int it = 0; it < 24; ++it) {
            T0 = 0.5f * (lo + hi);
            int c = gen_pass<false>(s_wa, gbase, T0, cand, lane);
            if (c < K_SEL)      hi = T0;
            else if (c > CAP)   lo = T0;
            else break;
        }
        m = gen_pass<true>(s_wa, gbase, T0, cand, lane);
    }

    // ---- fine histogram over m candidates ----
    #pragma unroll
    for (int j = lane; j < 256; j += 32) s_hist[w][j] = 0u;
    __syncwarp();
    for (int c = lane; c < m; c += 32) {
        float pert = inv_orderable((unsigned)(cand[c] >> 32));
        int q = qbin_of(pert);
        s_qb[w][c] = (unsigned char)q;
        atomicAdd(&s_hist[w][q], 1u);
    }
    __syncwarp();

    // ---- suffix scan: find boundary bin Bq, count above ----
    unsigned h[8], t = 0;
    #pragma unroll
    for (int j = 0; j < 8; ++j) { h[j] = s_hist[w][(lane << 3) + j]; t += h[j]; }
    unsigned x = t;
    #pragma unroll
    for (int off = 1; off < 32; off <<= 1) {
        unsigned y = __shfl_down_sync(0xFFFFFFFFu, x, off);
        if (lane + off < 32) x += y;
    }
    unsigned run = x - t;      // suffix over lanes > lane
    int  Bq_l = -1; unsigned above_l = 0;
    #pragma unroll
    for (int j = 7; j >= 0; --j) {
        unsigned inc = run + h[j];
        if (run < K_SEL && inc >= K_SEL) { Bq_l = (lane << 3) + j; above_l = run; }
        run = inc;
    }
    unsigned fb = __ballot_sync(0xFFFFFFFFu, Bq_l >= 0);
    int src = __ffs(fb) - 1;
    const int      Bq    = __shfl_sync(0xFFFFFFFFu, Bq_l, src);
    const unsigned above = __shfl_sync(0xFFFFFFFFu, above_l, src);
    const unsigned need  = K_SEL - above;

    // ---- exact boundary tie-break: top `need` of bin Bq by (key desc, d asc) ----
    #pragma unroll
    for (int j = lane; j < CAP / 32; j += 32) s_chosen[w][j] = 0u;
    __syncwarp();
    for (unsigned it = 0; it < need; ++it) {
        unsigned long long best = 0ull; int bpos = -1;
        for (int c = lane; c < m; c += 32) {
            if (s_qb[w][c] == (unsigned char)Bq &&
                !((s_chosen[w][c >> 5] >> (c & 31)) & 1u)) {
                unsigned long long v = cand[c];
                if (v > best) { best = v; bpos = c; }
            }
        }
        #pragma unroll
        for (int off = 16; off; off >>= 1) {
            unsigned long long ob = __shfl_down_sync(0xFFFFFFFFu, best, off);
            int op = __shfl_down_sync(0xFFFFFFFFu, bpos, off);
            if (ob > best) { best = ob; bpos = op; }
        }
        bpos = __shfl_sync(0xFFFFFFFFu, bpos, 0);
        if (lane == 0) s_chosen[w][bpos >> 5] |= 1u << (bpos & 31);
        __syncwarp();
    }

    // ---- gather the 32 selected indices (unordered) ----
    int sbase = 0;
    const unsigned ltmask = (1u << lane) - 1u;
    for (int c0 = 0; c0 < m; c0 += 32) {
        int c = c0 + lane;
        bool pred = false; unsigned d = 0;
        if (c < m) {
            bool win = ((int)s_qb[w][c] > Bq) ||
                       (((s_chosen[w][c >> 5] >> (c & 31)) & 1u) != 0u);
            if (win) { pred = true; d = ~(unsigned)(cand[c] & 0xFFFFFFFFull); }
        }
        unsigned bal = __ballot_sync(0xFFFFFFFFu, pred);
        if (pred) {
            int slot = sbase + __popc(bal & ltmask);
            if (slot < K_SEL) s_sel[w][slot] = d;
        }
        sbase += __popc(bal);
    }
    __syncwarp();

    // ---- bitonic sort 32 indices ascending -> ranks; write u16 scratch ----
    unsigned v = s_sel[w][lane];
    #pragma unroll
    for (int k = 2; k <= 32; k <<= 1) {
        #pragma unroll
        for (int j = k >> 1; j > 0; j >>= 1) {
            unsigned p = __shfl_xor_sync(0xFFFFFFFFu, v, j);
            bool up = ((lane & k) == 0);
            bool lower = ((lane & j) == 0);
            v = (lower == up) ? min(v, p) : max(v, p);
        }
    }
    g_sel[(size_t)row * K_SEL + lane] = (unsigned short)v;
}

// =============================================================================
// Kernel 2: per-b reduce over 920 samples via index gather, then bbox.
// Same deterministic summation order as the passing round-1 kernel.
// =============================================================================
__global__ void __launch_bounds__(256)
finalize_kernel(const float* __restrict__ wa, float* __restrict__ out) {
    const int b = blockIdx.x;
    const int tid = threadIdx.x;
    const int lane = tid & 31;   // k
    const int w = tid >> 5;      // 8 sample groups
    __shared__ float s_wa[D_SZ];
    __shared__ float red[8][32];

    const float* warow = wa + (size_t)b * D_SZ;
    for (int d = tid; d < D_SZ; d += 256) s_wa[d] = warow[d];
    __syncthreads();

    const unsigned short* base = g_sel + (size_t)b * D_SZ * K_SEL;
    float acc = 0.0f;
    for (int n = w; n < D_SZ; n += 8) {
        unsigned idx = base[n * K_SEL + lane];
        acc += s_wa[idx];
    }
    red[w][lane] = acc;
    __syncthreads();

    if (w == 0) {
        float s = 0.0f;
        #pragma unroll
        for (int i = 0; i < 8; i++) s += red[i][lane];
        s = s / (float)D_SZ;

        float r = floorf(__fdiv_rn(s, 40.0f));
        float c = __fadd_rn(s, -__fmul_rn(r, 40.0f));   // jnp.mod(s, 40)
        float x0 = __fmul_rn((c < 1.0f) ? c : (c - 1.0f), 32.0f);
        float y0 = __fmul_rn((r < 1.0f) ? r : (r - 1.0f), 32.0f);
        float x1 = __fmul_rn((c < 1.0f) ? (c + 2.0f) : (c + 1.0f), 32.0f);
        float y1 = __fmul_rn(r + 2.0f, 32.0f);
        reinterpret_cast<float4*>(out)[b * K_SEL + lane] = make_float4(x0, y0, x1, y1);
    }
}

extern "C" void kernel_launch(void* const* d_in, const int* in_sizes, int n_in,
                              void* d_out, int out_size) {
    (void)in_sizes; (void)n_in; (void)out_size;
    const float* weight_attn = (const float*)d_in[2];   // (64, 23, 40)
    float* out = (float*)d_out;                          // (64, 32, 4)

    row_topk_kernel<<<NROWS / WARPS_PER_CTA, THREADS>>>(weight_attn);
    finalize_kernel<<<B_SZ, 256>>>(weight_attn, out);
}

// round 7
// speedup vs baseline: 1.8619x; 1.1661x over previous
#include <cuda_runtime.h>
#include <cstdint>

// ---------------- problem constants ----------------
#define B_SZ    64
#define D_SZ    920          // 23*40
#define K_SEL   32
#define NROWS   (B_SZ * D_SZ)      // 58880 sample-rows (b, n)
#define WARPS_PER_CTA 8
#define THREADS (WARPS_PER_CTA * 32)
#define CAP     256
#define T0F     0.90f        // prefilter threshold (exact-count fallback below)

// scratch (all __device__ globals; no allocations)
__device__ unsigned short g_sel[NROWS * K_SEL];      // 3.68 MB selected indices
__device__ unsigned       g_tbits[B_SZ * D_SZ];      // 235 KB bit-thresholds
__device__ float          g_red[B_SZ * 8 * K_SEL];   // 64 KB stage-1 partials

// ---------------- threefry2x32, key=(0,1), partitionable fold ----------------
__device__ __forceinline__ unsigned tf_bits(unsigned ctr) {
    unsigned x0 = 0u, x1 = ctr;
    const unsigned k0 = 0u, k1 = 1u, kx = 0x1BD11BDBu;
    x0 += k0; x1 += k1;
#define TFR(r) { x0 += x1; x1 = __funnelshift_l(x1, x1, (r)); x1 ^= x0; }
    TFR(13) TFR(15) TFR(26) TFR(6)
    x0 += k1; x1 += kx + 1u;
    TFR(17) TFR(29) TFR(16) TFR(24)
    x0 += kx; x1 += k0 + 2u;
    TFR(13) TFR(15) TFR(26) TFR(6)
    x0 += k0; x1 += k1 + 3u;
    TFR(17) TFR(29) TFR(16) TFR(24)
    x0 += k1; x1 += kx + 4u;
#undef TFR
    return x0 ^ x1;
}

// ---------------- XLA ErfInv32 (identical numerics to passing rounds) --------
__device__ __forceinline__ float erfinv_xla(float x) {
    float w = -log1pf(-__fmul_rn(x, x));
    float p;
    if (w < 5.0f) {
        w = w - 2.5f;
        p = 2.81022636e-08f;
        p = fmaf(p, w, 3.43273939e-07f);
        p = fmaf(p, w, -3.5233877e-06f);
        p = fmaf(p, w, -4.39150654e-06f);
        p = fmaf(p, w, 0.00021858087f);
        p = fmaf(p, w, -0.00125372503f);
        p = fmaf(p, w, -0.00417768164f);
        p = fmaf(p, w, 0.246640727f);
        p = fmaf(p, w, 1.50140941f);
    } else {
        w = sqrtf(w) - 3.0f;
        p = -0.000200214257f;
        p = fmaf(p, w, 0.000100950558f);
        p = fmaf(p, w, 0.00134934322f);
        p = fmaf(p, w, -0.00367342844f);
        p = fmaf(p, w, 0.00573950773f);
        p = fmaf(p, w, -0.0076224613f);
        p = fmaf(p, w, 0.00943887047f);
        p = fmaf(p, w, 1.00167406f);
        p = fmaf(p, w, 2.83297682f);
    }
    return __fmul_rn(p, x);
}

// exact perturbed value from the 23 uniform bits (must match all rounds' path)
__device__ __forceinline__ float pert_from_v23(unsigned v23, float wad) {
    float f = __uint_as_float(v23 | 0x3F800000u) - 1.0f;   // [0,1)
    float u = __fadd_rn(__fmul_rn(f, 2.0f), -0.99999994f);
    float nrm = __fmul_rn(1.41421356f, erfinv_xla(u));
    return __fadd_rn(wad, __fmul_rn(nrm, 0.1f));
}

__device__ __forceinline__ unsigned orderable(float v) {
    unsigned u = __float_as_uint(v);
    return (u & 0x80000000u) ? ~u : (u | 0x80000000u);
}
__device__ __forceinline__ int qbin_of(float pert) {
    int q = (int)fmaf(pert, 600.0f, -520.0f);
    return min(255, max(0, q));
}

// =============================================================================
// Kernel 0: per-(b,d) minimal v23 with pert(v23) > T0, via fixed 23-step exact
// bisection over the monotone map v23 -> pert. Stored with 64-ULP conservative
// slack (superset filter; exactness restored downstream on candidates).
// =============================================================================
__global__ void __launch_bounds__(256)
thresh_kernel(const float* __restrict__ wa) {
    int i = blockIdx.x * 256 + threadIdx.x;
    if (i >= B_SZ * D_SZ) return;
    float wad = wa[i];
    unsigned lo = 0u, hi = 0x800000u;     // hi sentinel: no v qualifies
    #pragma unroll 1
    for (int it = 0; it < 24; ++it) {     // 2^23 range -> 23 steps suffice
        if (lo >= hi) break;
        unsigned mid = (lo + hi) >> 1;
        if (pert_from_v23(mid, wad) > T0F) hi = mid; else lo = mid + 1u;
    }
    g_tbits[i] = (lo >= 64u) ? (lo - 64u) : 0u;
}

// exact-pert generation pass (fallback only; stores (bits, d) pairs)
template<bool STORE>
__device__ __forceinline__ int gen_exact(const float* s_wa, unsigned gbase, float T,
                                         unsigned long long* cand, int lane) {
    const unsigned ltmask = (1u << lane) - 1u;
    int base = 0;
    for (int i = 0; i < 29; ++i) {
        int d = (i << 5) + lane;
        bool valid = (d < D_SZ);
        unsigned bits = valid ? tf_bits(gbase + (unsigned)d) : 0u;
        float pert = valid ? pert_from_v23(bits >> 9, s_wa[d]) : -1e30f;
        bool pred = valid && (pert > T);
        unsigned bal = __ballot_sync(0xFFFFFFFFu, pred);
        if (STORE && pred) {
            int slot = base + __popc(bal & ltmask);
            if (slot < CAP)
                cand[slot] = ((unsigned long long)bits << 32) | (unsigned)d;
        }
        base += __popc(bal);
    }
    return base;
}

// =============================================================================
// Kernel 1: warp-per-row, integer-only hot loop (threefry + bit compare),
// 4-way independent threefry chains per lane for ILP.
// =============================================================================
__global__ void __launch_bounds__(THREADS)
row_topk_kernel(const float* __restrict__ wa) {
    __shared__ float              s_wa[D_SZ];
    __shared__ unsigned           s_t[D_SZ];
    __shared__ unsigned long long s_cand[WARPS_PER_CTA][CAP];
    __shared__ unsigned           s_hist[WARPS_PER_CTA][256];
    __shared__ unsigned char      s_qb[WARPS_PER_CTA][CAP];
    __shared__ unsigned           s_sel[WARPS_PER_CTA][K_SEL];
    __shared__ unsigned           s_chosen[WARPS_PER_CTA][CAP / 32];

    const int tid  = threadIdx.x;
    const int w    = tid >> 5;
    const int lane = tid & 31;
    const int row  = blockIdx.x * WARPS_PER_CTA + w;
    const int b    = (blockIdx.x * WARPS_PER_CTA) / D_SZ;   // same b across CTA

    for (int d = tid; d < D_SZ; d += THREADS) {
        s_wa[d] = wa[(size_t)b * D_SZ + d];
        s_t[d]  = g_tbits[(size_t)b * D_SZ + d];
    }
    __syncthreads();            // the only block barrier

    unsigned long long* cand = s_cand[w];
    const unsigned gbase  = (unsigned)row * (unsigned)D_SZ;
    const unsigned ltmask = (1u << lane) - 1u;

    // ---- integer-only generate + prefilter (4 independent chains/lane) ----
    int m = 0;
    #pragma unroll 1
    for (int i = 0; i < 28; i += 4) {
        int d0 = (i << 5) + lane;
        unsigned bb0 = tf_bits(gbase + (unsigned)(d0));
        unsigned bb1 = tf_bits(gbase + (unsigned)(d0 + 32));
        unsigned bb2 = tf_bits(gbase + (unsigned)(d0 + 64));
        unsigned bb3 = tf_bits(gbase + (unsigned)(d0 + 96));
        bool p0 = (bb0 >> 9) >= s_t[d0];
        bool p1 = (bb1 >> 9) >= s_t[d0 + 32];
        bool p2 = (bb2 >> 9) >= s_t[d0 + 64];
        bool p3 = (bb3 >> 9) >= s_t[d0 + 96];
        unsigned bal;
        bal = __ballot_sync(0xFFFFFFFFu, p0);
        if (p0) { int s = m + __popc(bal & ltmask);
                  if (s < CAP) cand[s] = ((unsigned long long)bb0 << 32) | (unsigned)d0; }
        m += __popc(bal);
        bal = __ballot_sync(0xFFFFFFFFu, p1);
        if (p1) { int s = m + __popc(bal & ltmask);
                  if (s < CAP) cand[s] = ((unsigned long long)bb1 << 32) | (unsigned)(d0 + 32); }
        m += __popc(bal);
        bal = __ballot_sync(0xFFFFFFFFu, p2);
        if (p2) { int s = m + __popc(bal & ltmask);
                  if (s < CAP) cand[s] = ((unsigned long long)bb2 << 32) | (unsigned)(d0 + 64); }
        m += __popc(bal);
        bal = __ballot_sync(0xFFFFFFFFu, p3);
        if (p3) { int s = m + __popc(bal & ltmask);
                  if (s < CAP) cand[s] = ((unsigned long long)bb3 << 32) | (unsigned)(d0 + 96); }
        m += __popc(bal);
    }
    {   // tail d = 896 + lane, lane < 24
        int d = 896 + lane;
        bool valid = (d < D_SZ);
        unsigned bb = valid ? tf_bits(gbase + (unsigned)d) : 0u;
        bool p = valid && ((bb >> 9) >= s_t[d]);
        unsigned bal = __ballot_sync(0xFFFFFFFFu, p);
        if (p) { int s = m + __popc(bal & ltmask);
                 if (s < CAP) cand[s] = ((unsigned long long)bb << 32) | (unsigned)d; }
        m += __popc(bal);
    }

    // ---- exact pert/key conversion for candidates; exact above-T0 count ------
    auto convert = [&](int mm) -> int {
        int cnt = 0;
        for (int c = lane; c < mm; c += 32) {
            unsigned long long e = cand[c];
            unsigned bits = (unsigned)(e >> 32);
            unsigned d    = (unsigned)(e & 0xFFFFFFFFull);
            float pert = pert_from_v23(bits >> 9, s_wa[d]);
            cnt += (pert > T0F);
            cand[c] = ((unsigned long long)orderable(pert) << 32) | (unsigned)(~d);
            s_qb[w][c] = (unsigned char)qbin_of(pert);
        }
        __syncwarp();
        return __reduce_add_sync(0xFFFFFFFFu, cnt);
    };

    int mm = min(m, CAP);
    int mex = convert(mm);

    if (m > CAP || mex < K_SEL) {
        // exact fallback (never fires for this distribution): bisect a value
        // threshold with K_SEL <= count <= CAP using exact pert
        float lo = -0.7f, hi = 1.6f, T = T0F;
        #pragma unroll 1
        for (int it = 0; it < 24; ++it) {
            T = 0.5f * (lo + hi);
            int c = gen_exact<false>(s_wa, gbase, T, cand, lane);
            if (c < K_SEL)      hi = T;
            else if (c > CAP)   lo = T;
            else break;
        }
        m  = gen_exact<true>(s_wa, gbase, T, cand, lane);
        mm = min(m, CAP);
        convert(mm);
    }

    // ---- fine histogram over mm candidates ----
    #pragma unroll
    for (int j = lane; j < 256; j += 32) s_hist[w][j] = 0u;
    __syncwarp();
    for (int c = lane; c < mm; c += 32)
        atomicAdd(&s_hist[w][s_qb[w][c]], 1u);
    __syncwarp();

    // ---- suffix scan: boundary bin Bq, count strictly above ----
    unsigned h[8], t = 0;
    #pragma unroll
    for (int j = 0; j < 8; ++j) { h[j] = s_hist[w][(lane << 3) + j]; t += h[j]; }
    unsigned x = t;
    #pragma unroll
    for (int off = 1; off < 32; off <<= 1) {
        unsigned y = __shfl_down_sync(0xFFFFFFFFu, x, off);
        if (lane + off < 32) x += y;
    }
    unsigned run = x - t;
    int Bq_l = -1; unsigned above_l = 0;
    #pragma unroll
    for (int j = 7; j >= 0; --j) {
        unsigned inc = run + h[j];
        if (run < K_SEL && inc >= K_SEL) { Bq_l = (lane << 3) + j; above_l = run; }
        run = inc;
    }
    unsigned fb = __ballot_sync(0xFFFFFFFFu, Bq_l >= 0);
    int src = __ffs(fb) - 1;
    const int      Bq    = __shfl_sync(0xFFFFFFFFu, Bq_l, src);
    const unsigned above = __shfl_sync(0xFFFFFFFFu, above_l, src);
    const unsigned need  = K_SEL - above;

    // ---- exact boundary tie-break: top `need` of bin Bq by (key desc, d asc) --
    #pragma unroll
    for (int j = lane; j < CAP / 32; j += 32) s_chosen[w][j] = 0u;
    __syncwarp();
    for (unsigned it = 0; it < need; ++it) {
        unsigned long long best = 0ull; int bpos = -1;
        for (int c = lane; c < mm; c += 32) {
            if (s_qb[w][c] == (unsigned char)Bq &&
                !((s_chosen[w][c >> 5] >> (c & 31)) & 1u)) {
                unsigned long long v = cand[c];
                if (v > best) { best = v; bpos = c; }
            }
        }
        #pragma unroll
        for (int off = 16; off; off >>= 1) {
            unsigned long long ob = __shfl_down_sync(0xFFFFFFFFu, best, off);
            int op = __shfl_down_sync(0xFFFFFFFFu, bpos, off);
            if (ob > best) { best = ob; bpos = op; }
        }
        bpos = __shfl_sync(0xFFFFFFFFu, bpos, 0);
        if (lane == 0 && bpos >= 0)                       // defensive: no wild write
            s_chosen[w][bpos >> 5] |= 1u << (bpos & 31);
        __syncwarp();
    }

    // ---- gather 32 selected indices (unordered) ----
    int sbase = 0;
    for (int c0 = 0; c0 < mm; c0 += 32) {
        int c = c0 + lane;
        bool pred = false; unsigned d = 0;
        if (c < mm) {
            bool win = ((int)s_qb[w][c] > Bq) ||
                       (((s_chosen[w][c >> 5] >> (c & 31)) & 1u) != 0u);
            if (win) { pred = true; d = ~(unsigned)(cand[c] & 0xFFFFFFFFull); }
        }
        unsigned bal = __ballot_sync(0xFFFFFFFFu, pred);
        if (pred) {
            int slot = sbase + __popc(bal & ltmask);
            if (slot < K_SEL) s_sel[w][slot] = d;
        }
        sbase += __popc(bal);
    }
    __syncwarp();

    // ---- bitonic sort 32 indices ascending -> ranks; u16 scratch write ----
    unsigned v = s_sel[w][lane];
    #pragma unroll
    for (int k = 2; k <= 32; k <<= 1) {
        #pragma unroll
        for (int j = k >> 1; j > 0; j >>= 1) {
            unsigned p = __shfl_xor_sync(0xFFFFFFFFu, v, j);
            bool up = ((lane & k) == 0);
            bool lower = ((lane & j) == 0);
            v = (lower == up) ? min(v, p) : max(v, p);
        }
    }
    g_sel[(size_t)row * K_SEL + lane] = (unsigned short)v;
}

// =============================================================================
// Kernel 2a: per-(b,w) partial sums — EXACT same per-warp add order as the
// passing rounds. grid (64, 2), block 128; warp handles w = blockIdx.y*4 + wid.
// =============================================================================
__global__ void __launch_bounds__(128)
reduce_kernel(const float* __restrict__ wa) {
    const int b    = blockIdx.x;
    const int w    = blockIdx.y * 4 + (threadIdx.x >> 5);
    const int lane = threadIdx.x & 31;
    __shared__ float s_wa[D_SZ];
    for (int d = threadIdx.x; d < D_SZ; d += 128) s_wa[d] = wa[(size_t)b * D_SZ + d];
    __syncthreads();

    const unsigned short* base = g_sel + (size_t)b * D_SZ * K_SEL;
    float acc = 0.0f;
    #pragma unroll 1
    for (int n = w; n < D_SZ; n += 8)
        acc += s_wa[base[n * K_SEL + lane]];
    g_red[((size_t)b * 8 + w) * K_SEL + lane] = acc;
}

// =============================================================================
// Kernel 2b: combine 8 partials in the EXACT same order, then bbox.
// =============================================================================
__global__ void __launch_bounds__(32)
bbox_kernel(float* __restrict__ out) {
    const int b = blockIdx.x;
    const int lane = threadIdx.x;   // k
    float s = 0.0f;
    #pragma unroll
    for (int i = 0; i < 8; i++) s += g_red[((size_t)b * 8 + i) * K_SEL + lane];
    s = s / (float)D_SZ;

    float r = floorf(__fdiv_rn(s, 40.0f));
    float c = __fadd_rn(s, -__fmul_rn(r, 40.0f));   // jnp.mod(s, 40)
    float x0 = __fmul_rn((c < 1.0f) ? c : (c - 1.0f), 32.0f);
    float y0 = __fmul_rn((r < 1.0f) ? r : (r - 1.0f), 32.0f);
    float x1 = __fmul_rn((c < 1.0f) ? (c + 2.0f) : (c + 1.0f), 32.0f);
    float y1 = __fmul_rn(r + 2.0f, 32.0f);
    reinterpret_cast<float4*>(out)[b * K_SEL + lane] = make_float4(x0, y0, x1, y1);
}

extern "C" void kernel_launch(void* const* d_in, const int* in_sizes, int n_in,
                              void* d_out, int out_size) {
    (void)in_sizes; (void)n_in; (void)out_size;
    const float* weight_attn = (const float*)d_in[2];   // (64, 23, 40)
    float* out = (float*)d_out;                          // (64, 32, 4)

    thresh_kernel<<<(B_SZ * D_SZ + 255) / 256, 256>>>(weight_attn);
    row_topk_kernel<<<NROWS / WARPS_PER_CTA, THREADS>>>(weight_attn);
    reduce_kernel<<<dim3(B_SZ, 2), 128>>>(weight_attn);
    bbox_kernel<<<B_SZ, 32>>>(out);
}

// round 9
// speedup vs baseline: 2.0718x; 1.1128x over previous
#include <cuda_runtime.h>
#include <cstdint>

// ---------------- problem constants ----------------
#define B_SZ    64
#define D_SZ    920          // 23*40
#define K_SEL   32
#define NROWS   (B_SZ * D_SZ)      // 58880 sample-rows (b, n)
#define WARPS_PER_CTA 8
#define THREADS (WARPS_PER_CTA * 32)
#define CAP     256
#define T0F     0.90f        // prefilter threshold (exact-count fallback below)
#define ACT_PAD 1024

// scratch (all __device__ globals; no allocations)
__device__ unsigned short      g_sel[NROWS * K_SEL];       // 3.68 MB selected indices
__device__ unsigned long long  g_act[B_SZ * D_SZ];         // per-b active list (tf<<32|d)
__device__ int                 g_actcnt[B_SZ];             // per-b active counts
__device__ float               g_red[B_SZ * 8 * K_SEL];    // stage-1 partials

// ---------------- threefry2x32, key=(0,1), partitionable fold ----------------
__device__ __forceinline__ unsigned tf_bits(unsigned ctr) {
    unsigned x0 = 0u, x1 = ctr;
    const unsigned k0 = 0u, k1 = 1u, kx = 0x1BD11BDBu;
    x0 += k0; x1 += k1;
#define TFR(r) { x0 += x1; x1 = __funnelshift_l(x1, x1, (r)); x1 ^= x0; }
    TFR(13) TFR(15) TFR(26) TFR(6)
    x0 += k1; x1 += kx + 1u;
    TFR(17) TFR(29) TFR(16) TFR(24)
    x0 += kx; x1 += k0 + 2u;
    TFR(13) TFR(15) TFR(26) TFR(6)
    x0 += k0; x1 += k1 + 3u;
    TFR(17) TFR(29) TFR(16) TFR(24)
    x0 += k1; x1 += kx + 4u;
#undef TFR
    return x0 ^ x1;
}

// ---------------- XLA ErfInv32 (identical numerics to passing rounds) --------
__device__ __forceinline__ float erfinv_xla(float x) {
    float w = -log1pf(-__fmul_rn(x, x));
    float p;
    if (w < 5.0f) {
        w = w - 2.5f;
        p = 2.81022636e-08f;
        p = fmaf(p, w, 3.43273939e-07f);
        p = fmaf(p, w, -3.5233877e-06f);
        p = fmaf(p, w, -4.39150654e-06f);
        p = fmaf(p, w, 0.00021858087f);
        p = fmaf(p, w, -0.00125372503f);
        p = fmaf(p, w, -0.00417768164f);
        p = fmaf(p, w, 0.246640727f);
        p = fmaf(p, w, 1.50140941f);
    } else {
        w = sqrtf(w) - 3.0f;
        p = -0.000200214257f;
        p = fmaf(p, w, 0.000100950558f);
        p = fmaf(p, w, 0.00134934322f);
        p = fmaf(p, w, -0.00367342844f);
        p = fmaf(p, w, 0.00573950773f);
        p = fmaf(p, w, -0.0076224613f);
        p = fmaf(p, w, 0.00943887047f);
        p = fmaf(p, w, 1.00167406f);
        p = fmaf(p, w, 2.83297682f);
    }
    return __fmul_rn(p, x);
}

// exact perturbed value from the 23 uniform bits (must match all rounds' path)
__device__ __forceinline__ float pert_from_v23(unsigned v23, float wad) {
    float f = __uint_as_float(v23 | 0x3F800000u) - 1.0f;   // [0,1)
    float u = __fadd_rn(__fmul_rn(f, 2.0f), -0.99999994f);
    float nrm = __fmul_rn(1.41421356f, erfinv_xla(u));
    return __fadd_rn(wad, __fmul_rn(nrm, 0.1f));
}

__device__ __forceinline__ unsigned orderable(float v) {
    unsigned u = __float_as_uint(v);
    return (u & 0x80000000u) ? ~u : (u | 0x80000000u);
}
__device__ __forceinline__ int qbin_of(float pert) {
    int q = (int)fmaf(pert, 600.0f, -520.0f);
    return min(255, max(0, q));
}

// =============================================================================
// Kernel 0: one block per b. Per-d exact 23-step bisection for the minimal v23
// with pert > T0; d with NO qualifying v23 are dropped. Survivors compacted
// (block scan, d-ascending order — order is selection-neutral) into g_act[b]
// as (tfull<<32 | d), tfull = max(lo-64,0)<<9 (64-ULP conservative slack).
// =============================================================================
__global__ void __launch_bounds__(1024)
thresh_compact_kernel(const float* __restrict__ wa) {
    const int b   = blockIdx.x;
    const int tid = threadIdx.x;
    const int lane = tid & 31, w = tid >> 5;
    __shared__ unsigned s_wcnt[32];
    __shared__ unsigned s_wbase[32];

    bool active = false;
    unsigned tf = 0u;
    if (tid < D_SZ) {
        float wad = wa[(size_t)b * D_SZ + tid];
        unsigned lo = 0u, hi = 0x800000u;
        #pragma unroll 1
        for (int it = 0; it < 24; ++it) {
            if (lo >= hi) break;
            unsigned mid = (lo + hi) >> 1;
            if (pert_from_v23(mid, wad) > T0F) hi = mid; else lo = mid + 1u;
        }
        if (lo < 0x800000u) {            // qualification possible for some v23
            active = true;
            unsigned t = (lo >= 64u) ? (lo - 64u) : 0u;
            tf = t << 9;                 // compare against full 32-bit `bits`
        }
    }
    unsigned bal = __ballot_sync(0xFFFFFFFFu, active);
    if (lane == 0) s_wcnt[w] = __popc(bal);
    __syncthreads();
    if (w == 0) {                        // exclusive scan of 32 warp counts
        unsigned v = s_wcnt[lane], acc = v;
        #pragma unroll
        for (int off = 1; off < 32; off <<= 1) {
            unsigned y = __shfl_up_sync(0xFFFFFFFFu, acc, off);
            if (lane >= off) acc += y;
        }
        s_wbase[lane] = acc - v;
        if (lane == 31) g_actcnt[b] = (int)acc;
    }
    __syncthreads();
    if (active) {
        int pos = (int)s_wbase[w] + __popc(bal & ((1u << lane) - 1u));
        g_act[(size_t)b * D_SZ + pos] =
            ((unsigned long long)tf << 32) | (unsigned)tid;
    }
}

// exact-pert generation pass (fallback only; full d scan, independent of g_act)
template<bool STORE>
__device__ __forceinline__ int gen_exact(const float* s_wa, unsigned gbase, float T,
                                         unsigned long long* cand, int lane) {
    const unsigned ltmask = (1u << lane) - 1u;
    int base = 0;
    for (int i = 0; i < 29; ++i) {
        int d = (i << 5) + lane;
        bool valid = (d < D_SZ);
        unsigned bits = valid ? tf_bits(gbase + (unsigned)d) : 0u;
        float pert = valid ? pert_from_v23(bits >> 9, s_wa[d]) : -1e30f;
        bool pred = valid && (pert > T);
        unsigned bal = __ballot_sync(0xFFFFFFFFu, pred);
        if (STORE && pred) {
            int slot = base + __popc(bal & ltmask);
            if (slot < CAP)
                cand[slot] = ((unsigned long long)bits << 32) | (unsigned)d;
        }
        base += __popc(bal);
    }
    return base;
}

// =============================================================================
// Kernel 1: warp-per-row; hot loop over the COMPACTED active list only
// (threefry + 32-bit compare), 4 independent chains per lane.
// =============================================================================
__global__ void __launch_bounds__(THREADS)
row_topk_kernel(const float* __restrict__ wa) {
    __shared__ float              s_wa[D_SZ];
    __shared__ unsigned long long s_act[ACT_PAD];
    __shared__ unsigned long long s_cand[WARPS_PER_CTA][CAP];
    __shared__ unsigned           s_hist[WARPS_PER_CTA][256];
    __shared__ unsigned char      s_qb[WARPS_PER_CTA][CAP];
    __shared__ unsigned           s_sel[WARPS_PER_CTA][K_SEL];
    __shared__ unsigned           s_chosen[WARPS_PER_CTA][CAP / 32];

    const int tid  = threadIdx.x;
    const int w    = tid >> 5;
    const int lane = tid & 31;
    const int row  = blockIdx.x * WARPS_PER_CTA + w;
    const int b    = (blockIdx.x * WARPS_PER_CTA) / D_SZ;   // same b across CTA

    const int nact = g_actcnt[b];
    for (int d = tid; d < D_SZ; d += THREADS)
        s_wa[d] = wa[(size_t)b * D_SZ + d];
    for (int j = tid; j < ACT_PAD; j += THREADS)
        s_act[j] = (j < nact) ? g_act[(size_t)b * D_SZ + j]
                              : 0xFFFFFFFF00000000ull;      // padding never matches
    __syncthreads();            // the only block barrier

    unsigned long long* cand = s_cand[w];
    const unsigned gbase  = (unsigned)row * (unsigned)D_SZ;
    const unsigned ltmask = (1u << lane) - 1u;

    // ---- integer-only generate over active list (4 chains/lane) ----
    int m = 0;
    #pragma unroll 1
    for (int j0 = 0; j0 < nact; j0 += 128) {
        int j = j0 + lane;
        unsigned long long e0 = s_act[j];
        unsigned long long e1 = s_act[j + 32];
        unsigned long long e2 = s_act[j + 64];
        unsigned long long e3 = s_act[j + 96];
        unsigned d0 = (unsigned)e0, d1 = (unsigned)e1,
                 d2 = (unsigned)e2, d3 = (unsigned)e3;
        unsigned bb0 = tf_bits(gbase + d0);
        unsigned bb1 = tf_bits(gbase + d1);
        unsigned bb2 = tf_bits(gbase + d2);
        unsigned bb3 = tf_bits(gbase + d3);
        bool p0 = (j      < nact) && (bb0 >= (unsigned)(e0 >> 32));
        bool p1 = (j + 32 < nact) && (bb1 >= (unsigned)(e1 >> 32));
        bool p2 = (j + 64 < nact) && (bb2 >= (unsigned)(e2 >> 32));
        bool p3 = (j + 96 < nact) && (bb3 >= (unsigned)(e3 >> 32));
        unsigned bal;
        bal = __ballot_sync(0xFFFFFFFFu, p0);
        if (p0) { int s = m + __popc(bal & ltmask);
                  if (s < CAP) cand[s] = ((unsigned long long)bb0 << 32) | d0; }
        m += __popc(bal);
        bal = __ballot_sync(0xFFFFFFFFu, p1);
        if (p1) { int s = m + __popc(bal & ltmask);
                  if (s < CAP) cand[s] = ((unsigned long long)bb1 << 32) | d1; }
        m += __popc(bal);
        bal = __ballot_sync(0xFFFFFFFFu, p2);
        if (p2) { int s = m + __popc(bal & ltmask);
                  if (s < CAP) cand[s] = ((unsigned long long)bb2 << 32) | d2; }
        m += __popc(bal);
        bal = __ballot_sync(0xFFFFFFFFu, p3);
        if (p3) { int s = m + __popc(bal & ltmask);
                  if (s < CAP) cand[s] = ((unsigned long long)bb3 << 32) | d3; }
        m += __popc(bal);
    }

    // ---- exact pert/key conversion for candidates; exact above-T0 count ------
    auto convert = [&](int mm) -> int {
        int cnt = 0;
        for (int c = lane; c < mm; c += 32) {
            unsigned long long e = cand[c];
            unsigned bits = (unsigned)(e >> 32);
            unsigned d    = (unsigned)(e & 0xFFFFFFFFull);
            float pert = pert_from_v23(bits >> 9, s_wa[d]);
            cnt += (pert > T0F);
            cand[c] = ((unsigned long long)orderable(pert) << 32) | (unsigned)(~d);
            s_qb[w][c] = (unsigned char)qbin_of(pert);
        }
        __syncwarp();
        return __reduce_add_sync(0xFFFFFFFFu, cnt);
    };

    int mm = min(m, CAP);
    int mex = convert(mm);

    if (m > CAP || mex < K_SEL) {
        // exact fallback (never fires for this distribution): bisect a value
        // threshold with K_SEL <= count <= CAP using exact pert over ALL d
        float lo = -0.7f, hi = 1.6f, T = T0F;
        #pragma unroll 1
        for (int it = 0; it < 24; ++it) {
            T = 0.5f * (lo + hi);
            int c = gen_exact<false>(s_wa, gbase, T, cand, lane);
            if (c < K_SEL)      hi = T;
            else if (c > CAP)   lo = T;
            else break;
        }
        m  = gen_exact<true>(s_wa, gbase, T, cand, lane);
        mm = min(m, CAP);
        convert(mm);
    }

    // ---- fine histogram over mm candidates ----
    #pragma unroll
    for (int j = lane; j < 256; j += 32) s_hist[w][j] = 0u;
    __syncwarp();
    for (int c = lane; c < mm; c += 32)
        atomicAdd(&s_hist[w][s_qb[w][c]], 1u);
    __syncwarp();

    // ---- suffix scan: boundary bin Bq, count strictly above ----
    unsigned h[8], t = 0;
    #pragma unroll
    for (int j = 0; j < 8; ++j) { h[j] = s_hist[w][(lane << 3) + j]; t += h[j]; }
    unsigned x = t;
    #pragma unroll
    for (int off = 1; off < 32; off <<= 1) {
        unsigned y = __shfl_down_sync(0xFFFFFFFFu, x, off);
        if (lane + off < 32) x += y;
    }
    unsigned run = x - t;
    int Bq_l = -1; unsigned above_l = 0;
    #pragma unroll
    for (int j = 7; j >= 0; --j) {
        unsigned inc = run + h[j];
        if (run < K_SEL && inc >= K_SEL) { Bq_l = (lane << 3) + j; above_l = run; }
        run = inc;
    }
    unsigned fb = __ballot_sync(0xFFFFFFFFu, Bq_l >= 0);
    int src = __ffs(fb) - 1;
    const int      Bq    = __shfl_sync(0xFFFFFFFFu, Bq_l, src);
    const unsigned above = __shfl_sync(0xFFFFFFFFu, above_l, src);
    const unsigned need  = K_SEL - above;

    // ---- exact boundary tie-break: top `need` of bin Bq by (key desc, d asc) --
    #pragma unroll
    for (int j = lane; j < CAP / 32; j += 32) s_chosen[w][j] = 0u;
    __syncwarp();
    for (unsigned it = 0; it < need; ++it) {
        unsigned long long best = 0ull; int bpos = -1;
        for (int c = lane; c < mm; c += 32) {
            if (s_qb[w][c] == (unsigned char)Bq &&
                !((s_chosen[w][c >> 5] >> (c & 31)) & 1u)) {
                unsigned long long v = cand[c];
                if (v > best) { best = v; bpos = c; }
            }
        }
        #pragma unroll
        for (int off = 16; off; off >>= 1) {
            unsigned long long ob = __shfl_down_sync(0xFFFFFFFFu, best, off);
            int op = __shfl_down_sync(0xFFFFFFFFu, bpos, off);
            if (ob > best) { best = ob; bpos = op; }
        }
        bpos = __shfl_sync(0xFFFFFFFFu, bpos, 0);
        if (lane == 0 && bpos >= 0)                       // defensive: no wild write
            s_chosen[w][bpos >> 5] |= 1u << (bpos & 31);
        __syncwarp();
    }

    // ---- gather 32 selected indices (unordered) ----
    int sbase = 0;
    for (int c0 = 0; c0 < mm; c0 += 32) {
        int c = c0 + lane;
        bool pred = false; unsigned d = 0;
        if (c < mm) {
            bool win = ((int)s_qb[w][c] > Bq) ||
                       (((s_chosen[w][c >> 5] >> (c & 31)) & 1u) != 0u);
            if (win) { pred = true; d = ~(unsigned)(cand[c] & 0xFFFFFFFFull); }
        }
        unsigned bal = __ballot_sync(0xFFFFFFFFu, pred);
        if (pred) {
            int slot = sbase + __popc(bal & ltmask);
            if (slot < K_SEL) s_sel[w][slot] = d;
        }
        sbase += __popc(bal);
    }
    __syncwarp();

    // ---- bitonic sort 32 indices ascending -> ranks; u16 scratch write ----
    unsigned v = s_sel[w][lane];
    #pragma unroll
    for (int k = 2; k <= 32; k <<= 1) {
        #pragma unroll
        for (int j = k >> 1; j > 0; j >>= 1) {
            unsigned p = __shfl_xor_sync(0xFFFFFFFFu, v, j);
            bool up = ((lane & k) == 0);
            bool lower = ((lane & j) == 0);
            v = (lower == up) ? min(v, p) : max(v, p);
        }
    }
    g_sel[(size_t)row * K_SEL + lane] = (unsigned short)v;
}

// =============================================================================
// Kernel 2a: per-(b,w) partial sums — EXACT same per-warp add order as the
// passing rounds. grid (64, 2), block 128; warp handles w = blockIdx.y*4 + wid.
// =============================================================================
__global__ void __launch_bounds__(128)
reduce_kernel(const float* __restrict__ wa) {
    const int b    = blockIdx.x;
    const int w    = blockIdx.y * 4 + (threadIdx.x >> 5);
    const int lane = threadIdx.x & 31;
    __shared__ float s_wa[D_SZ];
    for (int d = threadIdx.x; d < D_SZ; d += 128) s_wa[d] = wa[(size_t)b * D_SZ + d];
    __syncthreads();

    const unsigned short* base = g_sel + (size_t)b * D_SZ * K_SEL;
    float acc = 0.0f;
    #pragma unroll 1
    for (int n = w; n < D_SZ; n += 8)
        acc += s_wa[base[n * K_SEL + lane]];
    g_red[((size_t)b * 8 + w) * K_SEL + lane] = acc;
}

// =============================================================================
// Kernel 2b: combine 8 partials in the EXACT same order, then bbox.
// =============================================================================
__global__ void __launch_bounds__(32)
bbox_kernel(float* __restrict__ out) {
    const int b = blockIdx.x;
    const int lane = threadIdx.x;   // k
    float s = 0.0f;
    #pragma unroll
    for (int i = 0; i < 8; i++) s += g_red[((size_t)b * 8 + i) * K_SEL + lane];
    s = s / (float)D_SZ;

    float r = floorf(__fdiv_rn(s, 40.0f));
    float c = __fadd_rn(s, -__fmul_rn(r, 40.0f));   // jnp.mod(s, 40)
    float x0 = __fmul_rn((c < 1.0f) ? c : (c - 1.0f), 32.0f);
    float y0 = __fmul_rn((r < 1.0f) ? r : (r - 1.0f), 32.0f);
    float x1 = __fmul_rn((c < 1.0f) ? (c + 2.0f) : (c + 1.0f), 32.0f);
    float y1 = __fmul_rn(r + 2.0f, 32.0f);
    reinterpret_cast<float4*>(out)[b * K_SEL + lane] = make_float4(x0, y0, x1, y1);
}

extern "C" void kernel_launch(void* const* d_in, const int* in_sizes, int n_in,
                              void* d_out, int out_size) {
    (void)in_sizes; (void)n_in; (void)out_size;
    const float* weight_attn = (const float*)d_in[2];   // (64, 23, 40)
    float* out = (float*)d_out;                          // (64, 32, 4)

    thresh_compact_kernel<<<B_SZ, 1024>>>(weight_attn);
    row_topk_kernel<<<NROWS / WARPS_PER_CTA, THREADS>>>(weight_attn);
    reduce_kernel<<<dim3(B_SZ, 2), 128>>>(weight_attn);
    bbox_kernel<<<B_SZ, 32>>>(out);
}

// round 10
// speedup vs baseline: 2.1230x; 1.0247x over previous
#include <cuda_runtime.h>
#include <cstdint>

// ---------------- problem constants ----------------
#define B_SZ    64
#define D_SZ    920          // 23*40
#define K_SEL   32
#define NROWS   (B_SZ * D_SZ)      // 58880 sample-rows (b, n)
#define WARPS_PER_CTA 8
#define THREADS (WARPS_PER_CTA * 32)
#define CAP     128
#define T0F     0.90f        // prefilter threshold (exact-count fallback below)
#define ACT_PAD 1024

// scratch (all __device__ globals; no allocations)
__device__ unsigned short      g_sel[NROWS * K_SEL];       // 3.68 MB selected indices
__device__ unsigned long long  g_act[B_SZ * D_SZ];         // per-b active list (tf<<32|d)
__device__ int                 g_actcnt[B_SZ];             // per-b active counts

// ---------------- threefry2x32, key=(0,1), partitionable fold ----------------
__device__ __forceinline__ unsigned tf_bits(unsigned ctr) {
    unsigned x0 = 0u, x1 = ctr;
    const unsigned k0 = 0u, k1 = 1u, kx = 0x1BD11BDBu;
    x0 += k0; x1 += k1;
#define TFR(r) { x0 += x1; x1 = __funnelshift_l(x1, x1, (r)); x1 ^= x0; }
    TFR(13) TFR(15) TFR(26) TFR(6)
    x0 += k1; x1 += kx + 1u;
    TFR(17) TFR(29) TFR(16) TFR(24)
    x0 += kx; x1 += k0 + 2u;
    TFR(13) TFR(15) TFR(26) TFR(6)
    x0 += k0; x1 += k1 + 3u;
    TFR(17) TFR(29) TFR(16) TFR(24)
    x0 += k1; x1 += kx + 4u;
#undef TFR
    return x0 ^ x1;
}

// ---------------- XLA ErfInv32 (identical numerics to passing rounds) --------
__device__ __forceinline__ float erfinv_xla(float x) {
    float w = -log1pf(-__fmul_rn(x, x));
    float p;
    if (w < 5.0f) {
        w = w - 2.5f;
        p = 2.81022636e-08f;
        p = fmaf(p, w, 3.43273939e-07f);
        p = fmaf(p, w, -3.5233877e-06f);
        p = fmaf(p, w, -4.39150654e-06f);
        p = fmaf(p, w, 0.00021858087f);
        p = fmaf(p, w, -0.00125372503f);
        p = fmaf(p, w, -0.00417768164f);
        p = fmaf(p, w, 0.246640727f);
        p = fmaf(p, w, 1.50140941f);
    } else {
        w = sqrtf(w) - 3.0f;
        p = -0.000200214257f;
        p = fmaf(p, w, 0.000100950558f);
        p = fmaf(p, w, 0.00134934322f);
        p = fmaf(p, w, -0.00367342844f);
        p = fmaf(p, w, 0.00573950773f);
        p = fmaf(p, w, -0.0076224613f);
        p = fmaf(p, w, 0.00943887047f);
        p = fmaf(p, w, 1.00167406f);
        p = fmaf(p, w, 2.83297682f);
    }
    return __fmul_rn(p, x);
}

// exact perturbed value from the 23 uniform bits (must match all rounds' path)
__device__ __forceinline__ float pert_from_v23(unsigned v23, float wad) {
    float f = __uint_as_float(v23 | 0x3F800000u) - 1.0f;   // [0,1)
    float u = __fadd_rn(__fmul_rn(f, 2.0f), -0.99999994f);
    float nrm = __fmul_rn(1.41421356f, erfinv_xla(u));
    return __fadd_rn(wad, __fmul_rn(nrm, 0.1f));
}

__device__ __forceinline__ unsigned orderable(float v) {
    unsigned u = __float_as_uint(v);
    return (u & 0x80000000u) ? ~u : (u | 0x80000000u);
}
__device__ __forceinline__ int qbin_of(float pert) {
    int q = (int)fmaf(pert, 600.0f, -520.0f);
    return min(255, max(0, q));
}

// =============================================================================
// Kernel 0: one block per b. Per-d exact 23-step bisection for the minimal v23
// with pert > T0; d with NO qualifying v23 are dropped. Survivors compacted
// (block scan, d-ascending order — order is selection-neutral) into g_act[b]
// as (tfull<<32 | d), tfull = max(lo-64,0)<<9 (64-ULP conservative slack).
// =============================================================================
__global__ void __launch_bounds__(1024)
thresh_compact_kernel(const float* __restrict__ wa) {
    const int b   = blockIdx.x;
    const int tid = threadIdx.x;
    const int lane = tid & 31, w = tid >> 5;
    __shared__ unsigned s_wcnt[32];
    __shared__ unsigned s_wbase[32];

    bool active = false;
    unsigned tf = 0u;
    if (tid < D_SZ) {
        float wad = wa[(size_t)b * D_SZ + tid];
        unsigned lo = 0u, hi = 0x800000u;
        #pragma unroll 1
        for (int it = 0; it < 24; ++it) {
            if (lo >= hi) break;
            unsigned mid = (lo + hi) >> 1;
            if (pert_from_v23(mid, wad) > T0F) hi = mid; else lo = mid + 1u;
        }
        if (lo < 0x800000u) {            // qualification possible for some v23
            active = true;
            unsigned t = (lo >= 64u) ? (lo - 64u) : 0u;
            tf = t << 9;                 // compare against full 32-bit `bits`
        }
    }
    unsigned bal = __ballot_sync(0xFFFFFFFFu, active);
    if (lane == 0) s_wcnt[w] = __popc(bal);
    __syncthreads();
    if (w == 0) {                        // exclusive scan of 32 warp counts
        unsigned v = s_wcnt[lane], acc = v;
        #pragma unroll
        for (int off = 1; off < 32; off <<= 1) {
            unsigned y = __shfl_up_sync(0xFFFFFFFFu, acc, off);
            if (lane >= off) acc += y;
        }
        s_wbase[lane] = acc - v;
        if (lane == 31) g_actcnt[b] = (int)acc;
    }
    __syncthreads();
    if (active) {
        int pos = (int)s_wbase[w] + __popc(bal & ((1u << lane) - 1u));
        g_act[(size_t)b * D_SZ + pos] =
            ((unsigned long long)tf << 32) | (unsigned)tid;
    }
}

// exact-pert generation pass (fallback only; full d scan, independent of g_act)
template<bool STORE>
__device__ __forceinline__ int gen_exact(const float* s_wa, unsigned gbase, float T,
                                         unsigned long long* cand, int lane) {
    const unsigned ltmask = (1u << lane) - 1u;
    int base = 0;
    for (int i = 0; i < 29; ++i) {
        int d = (i << 5) + lane;
        bool valid = (d < D_SZ);
        unsigned bits = valid ? tf_bits(gbase + (unsigned)d) : 0u;
        float pert = valid ? pert_from_v23(bits >> 9, s_wa[d]) : -1e30f;
        bool pred = valid && (pert > T);
        unsigned bal = __ballot_sync(0xFFFFFFFFu, pred);
        if (STORE && pred) {
            int slot = base + __popc(bal & ltmask);
            if (slot < CAP)
                cand[slot] = ((unsigned long long)bits << 32) | (unsigned)d;
        }
        base += __popc(bal);
    }
    return base;
}

// =============================================================================
// Kernel 1: warp-per-row; hot loop over the COMPACTED active list only
// (threefry + 32-bit compare). Candidate insertion via per-warp smem atomic
// (order-independent selection math), 4-chain main loop + 1-chain remainder.
// =============================================================================
__global__ void __launch_bounds__(THREADS)
row_topk_kernel(const float* __restrict__ wa) {
    __shared__ float              s_wa[D_SZ];
    __shared__ unsigned long long s_act[ACT_PAD];
    __shared__ unsigned long long s_cand[WARPS_PER_CTA][CAP];
    __shared__ unsigned           s_hist[WARPS_PER_CTA][256];
    __shared__ unsigned char      s_qb[WARPS_PER_CTA][CAP];
    __shared__ unsigned           s_sel[WARPS_PER_CTA][K_SEL];
    __shared__ unsigned           s_chosen[WARPS_PER_CTA][CAP / 32];
    __shared__ int                s_cnt[WARPS_PER_CTA];

    const int tid  = threadIdx.x;
    const int w    = tid >> 5;
    const int lane = tid & 31;
    const int row  = blockIdx.x * WARPS_PER_CTA + w;
    const int b    = (blockIdx.x * WARPS_PER_CTA) / D_SZ;   // same b across CTA

    const int nact = g_actcnt[b];
    for (int d = tid; d < D_SZ; d += THREADS)
        s_wa[d] = wa[(size_t)b * D_SZ + d];
    for (int j = tid; j < nact; j += THREADS)
        s_act[j] = g_act[(size_t)b * D_SZ + j];
    if (lane == 0) s_cnt[w] = 0;
    __syncthreads();            // the only block barrier

    unsigned long long* cand = s_cand[w];
    const unsigned gbase  = (unsigned)row * (unsigned)D_SZ;
    const unsigned ltmask = (1u << lane) - 1u;

    // ---- integer-only generate over active list: 4 chains, no ballots ----
    const int nfull = nact & ~127;
    #pragma unroll 1
    for (int j0 = 0; j0 < nfull; j0 += 128) {
        int j = j0 + lane;
        unsigned long long e0 = s_act[j];
        unsigned long long e1 = s_act[j + 32];
        unsigned long long e2 = s_act[j + 64];
        unsigned long long e3 = s_act[j + 96];
        unsigned d0 = (unsigned)e0, d1 = (unsigned)e1,
                 d2 = (unsigned)e2, d3 = (unsigned)e3;
        unsigned bb0 = tf_bits(gbase + d0);
        unsigned bb1 = tf_bits(gbase + d1);
        unsigned bb2 = tf_bits(gbase + d2);
        unsigned bb3 = tf_bits(gbase + d3);
        if (bb0 >= (unsigned)(e0 >> 32)) {
            int s = atomicAdd(&s_cnt[w], 1);
            if (s < CAP) cand[s] = ((unsigned long long)bb0 << 32) | d0;
        }
        if (bb1 >= (unsigned)(e1 >> 32)) {
            int s = atomicAdd(&s_cnt[w], 1);
            if (s < CAP) cand[s] = ((unsigned long long)bb1 << 32) | d1;
        }
        if (bb2 >= (unsigned)(e2 >> 32)) {
            int s = atomicAdd(&s_cnt[w], 1);
            if (s < CAP) cand[s] = ((unsigned long long)bb2 << 32) | d2;
        }
        if (bb3 >= (unsigned)(e3 >> 32)) {
            int s = atomicAdd(&s_cnt[w], 1);
            if (s < CAP) cand[s] = ((unsigned long long)bb3 << 32) | d3;
        }
    }
    #pragma unroll 1
    for (int j0 = nfull; j0 < nact; j0 += 32) {     // remainder, 1 chain
        int j = j0 + lane;
        if (j < nact) {
            unsigned long long e = s_act[j];
            unsigned d = (unsigned)e;
            unsigned bb = tf_bits(gbase + d);
            if (bb >= (unsigned)(e >> 32)) {
                int s = atomicAdd(&s_cnt[w], 1);
                if (s < CAP) cand[s] = ((unsigned long long)bb << 32) | d;
            }
        }
    }
    __syncwarp();
    int m = s_cnt[w];

    // ---- exact pert/key conversion for candidates; exact above-T0 count ------
    auto convert = [&](int mm) -> int {
        int cnt = 0;
        for (int c = lane; c < mm; c += 32) {
            unsigned long long e = cand[c];
            unsigned bits = (unsigned)(e >> 32);
            unsigned d    = (unsigned)(e & 0xFFFFFFFFull);
            float pert = pert_from_v23(bits >> 9, s_wa[d]);
            cnt += (pert > T0F);
            cand[c] = ((unsigned long long)orderable(pert) << 32) | (unsigned)(~d);
            s_qb[w][c] = (unsigned char)qbin_of(pert);
        }
        __syncwarp();
        return __reduce_add_sync(0xFFFFFFFFu, cnt);
    };

    int mm = min(m, CAP);
    int mex = convert(mm);

    if (m > CAP || mex < K_SEL) {
        // exact fallback (never fires for this distribution): bisect a value
        // threshold with K_SEL <= count <= CAP using exact pert over ALL d
        float lo = -0.7f, hi = 1.6f, T = T0F;
        #pragma unroll 1
        for (int it = 0; it < 24; ++it) {
            T = 0.5f * (lo + hi);
            int c = gen_exact<false>(s_wa, gbase, T, cand, lane);
            if (c < K_SEL)      hi = T;
            else if (c > CAP)   lo = T;
            else break;
        }
        m  = gen_exact<true>(s_wa, gbase, T, cand, lane);
        mm = min(m, CAP);
        convert(mm);
    }

    // ---- fine histogram over mm candidates ----
    #pragma unroll
    for (int j = lane; j < 256; j += 32) s_hist[w][j] = 0u;
    __syncwarp();
    for (int c = lane; c < mm; c += 32)
        atomicAdd(&s_hist[w][s_qb[w][c]], 1u);
    __syncwarp();

    // ---- suffix scan: boundary bin Bq, count strictly above ----
    unsigned h[8], t = 0;
    #pragma unroll
    for (int j = 0; j < 8; ++j) { h[j] = s_hist[w][(lane << 3) + j]; t += h[j]; }
    unsigned x = t;
    #pragma unroll
    for (int off = 1; off < 32; off <<= 1) {
        unsigned y = __shfl_down_sync(0xFFFFFFFFu, x, off);
        if (lane + off < 32) x += y;
    }
    unsigned run = x - t;
    int Bq_l = -1; unsigned above_l = 0;
    #pragma unroll
    for (int j = 7; j >= 0; --j) {
        unsigned inc = run + h[j];
        if (run < K_SEL && inc >= K_SEL) { Bq_l = (lane << 3) + j; above_l = run; }
        run = inc;
    }
    unsigned fb = __ballot_sync(0xFFFFFFFFu, Bq_l >= 0);
    int src = __ffs(fb) - 1;
    const int      Bq    = __shfl_sync(0xFFFFFFFFu, Bq_l, src);
    const unsigned above = __shfl_sync(0xFFFFFFFFu, above_l, src);
    const unsigned need  = K_SEL - above;

    // ---- exact boundary tie-break: top `need` of bin Bq by (key desc, d asc) --
    #pragma unroll
    for (int j = lane; j < CAP / 32; j += 32) s_chosen[w][j] = 0u;
    __syncwarp();
    for (unsigned it = 0; it < need; ++it) {
        unsigned long long best = 0ull; int bpos = -1;
        for (int c = lane; c < mm; c += 32) {
            if (s_qb[w][c] == (unsigned char)Bq &&
                !((s_chosen[w][c >> 5] >> (c & 31)) & 1u)) {
                unsigned long long v = cand[c];
                if (v > best) { best = v; bpos = c; }
            }
        }
        #pragma unroll
        for (int off = 16; off; off >>= 1) {
            unsigned long long ob = __shfl_down_sync(0xFFFFFFFFu, best, off);
            int op = __shfl_down_sync(0xFFFFFFFFu, bpos, off);
            if (ob > best) { best = ob; bpos = op; }
        }
        bpos = __shfl_sync(0xFFFFFFFFu, bpos, 0);
        if (lane == 0 && bpos >= 0)                       // defensive: no wild write
            s_chosen[w][bpos >> 5] |= 1u << (bpos & 31);
        __syncwarp();
    }

    // ---- gather 32 selected indices (unordered) ----
    int sbase = 0;
    for (int c0 = 0; c0 < mm; c0 += 32) {
        int c = c0 + lane;
        bool pred = false; unsigned d = 0;
        if (c < mm) {
            bool win = ((int)s_qb[w][c] > Bq) ||
                       (((s_chosen[w][c >> 5] >> (c & 31)) & 1u) != 0u);
            if (win) { pred = true; d = ~(unsigned)(cand[c] & 0xFFFFFFFFull); }
        }
        unsigned bal = __ballot_sync(0xFFFFFFFFu, pred);
        if (pred) {
            int slot = sbase + __popc(bal & ltmask);
            if (slot < K_SEL) s_sel[w][slot] = d;
        }
        sbase += __popc(bal);
    }
    __syncwarp();

    // ---- bitonic sort 32 indices ascending -> ranks; u16 scratch write ----
    unsigned v = s_sel[w][lane];
    #pragma unroll
    for (int k = 2; k <= 32; k <<= 1) {
        #pragma unroll
        for (int j = k >> 1; j > 0; j >>= 1) {
            unsigned p = __shfl_xor_sync(0xFFFFFFFFu, v, j);
            bool up = ((lane & k) == 0);
            bool lower = ((lane & j) == 0);
            v = (lower == up) ? min(v, p) : max(v, p);
        }
    }
    g_sel[(size_t)row * K_SEL + lane] = (unsigned short)v;
}

// =============================================================================
// Kernel 2: fused reduce + bbox, one block per b. Per-warp add order is
// EXACTLY the passing rounds' (n = w, w+8, ... sequential adds), with 8-way
// independent-load unrolling to break the gather latency chain. Warp 0 then
// combines the 8 partials in the exact same order and emits the bbox.
// =============================================================================
__global__ void __launch_bounds__(256)
finalize_kernel(const float* __restrict__ wa, float* __restrict__ out) {
    const int b    = blockIdx.x;
    const int tid  = threadIdx.x;
    const int w    = tid >> 5;      // 8 sample groups
    const int lane = tid & 31;      // k
    __shared__ float s_wa[D_SZ];
    __shared__ float red[8][32];

    for (int d = tid; d < D_SZ; d += 256) s_wa[d] = wa[(size_t)b * D_SZ + d];
    __syncthreads();

    const unsigned short* base = g_sel + (size_t)b * D_SZ * K_SEL;
    float acc = 0.0f;
    int i = 0;
    #pragma unroll 1
    for (; i + 8 <= 115; i += 8) {          // n = w + 8*(i+t), t = 0..7
        unsigned i0 = base[(w + 8 * (i + 0)) * K_SEL + lane];
        unsigned i1 = base[(w + 8 * (i + 1)) * K_SEL + lane];
        unsigned i2 = base[(w + 8 * (i + 2)) * K_SEL + lane];
        unsigned i3 = base[(w + 8 * (i + 3)) * K_SEL + lane];
        unsigned i4 = base[(w + 8 * (i + 4)) * K_SEL + lane];
        unsigned i5 = base[(w + 8 * (i + 5)) * K_SEL + lane];
        unsigned i6 = base[(w + 8 * (i + 6)) * K_SEL + lane];
        unsigned i7 = base[(w + 8 * (i + 7)) * K_SEL + lane];
        float v0 = s_wa[i0], v1 = s_wa[i1], v2 = s_wa[i2], v3 = s_wa[i3];
        float v4 = s_wa[i4], v5 = s_wa[i5], v6 = s_wa[i6], v7 = s_wa[i7];
        acc += v0; acc += v1; acc += v2; acc += v3;     // exact serial order
        acc += v4; acc += v5; acc += v6; acc += v7;
    }
    #pragma unroll 1
    for (; i < 115; ++i)
        acc += s_wa[base[(w + 8 * i) * K_SEL + lane]];
    red[w][lane] = acc;
    __syncthreads();

    if (w == 0) {
        float s = 0.0f;
        #pragma unroll
        for (int j = 0; j < 8; j++) s += red[j][lane];
        s = s / (float)D_SZ;

        float r = floorf(__fdiv_rn(s, 40.0f));
        float c = __fadd_rn(s, -__fmul_rn(r, 40.0f));   // jnp.mod(s, 40)
        float x0 = __fmul_rn((c < 1.0f) ? c : (c - 1.0f), 32.0f);
        float y0 = __fmul_rn((r < 1.0f) ? r : (r - 1.0f), 32.0f);
        float x1 = __fmul_rn((c < 1.0f) ? (c + 2.0f) : (c + 1.0f), 32.0f);
        float y1 = __fmul_rn(r + 2.0f, 32.0f);
        reinterpret_cast<float4*>(out)[b * K_SEL + lane] = make_float4(x0, y0, x1, y1);
    }
}

extern "C" void kernel_launch(void* const* d_in, const int* in_sizes, int n_in,
                              void* d_out, int out_size) {
    (void)in_sizes; (void)n_in; (void)out_size;
    const float* weight_attn = (const float*)d_in[2];   // (64, 23, 40)
    float* out = (float*)d_out;                          // (64, 32, 4)

    thresh_compact_kernel<<<B_SZ, 1024>>>(weight_attn);
    row_topk_kernel<<<NROWS / WARPS_PER_CTA, THREADS>>>(weight_attn);
    finalize_kernel<<<B_SZ, 256>>>(weight_attn, out);
}